// round 14
// baseline (speedup 1.0000x reference)
#include <cuda_runtime.h>
#include <cuda_bf16.h>

// ---------------------------------------------------------------------------
// SRF layer: grouped conv, Gaussian-Hermite separable basis mixed by alphas.
// 128 threads/block = 64 column-pairs x 2 output-channel halves (4 o each).
// Triple-buffered chunk staging, one __syncthreads per chunk (verified R12).
// R14: row_step restructured — mixing fused per input channel so the hh[4][3]
// intermediate (24 live regs) disappears: per ch, compute 3 tap-sums (th) and
// immediately accumulate into 12 independent m-chains (alpha loads batched
// 6-wide). Identical instruction counts; smaller live set -> ptxas headroom.
// ---------------------------------------------------------------------------

#define H 384
#define W 384
#define B 16
#define INC 20
#define OUTC 40
#define NG 5
#define ICG 4
#define OCG 8
#define OH 4           // out channels per thread (OCG/2)
#define NB 6
#define SH 32          // strip height (384/32 = 12 strips)
#define SROW 136       // smem floats per (row,ch) (134 used, padded)
#define NCP 268        // float2 copy slots per row (4ch x 67)

__device__ float2 g_dp[NG][3][5];
__device__ float2 g_alpha[NG][NB][ICG][OCG];

typedef unsigned long long ull;

__device__ __forceinline__ ull pk2(float a, float b) {
    ull r; asm("mov.b64 %0, {%1, %2};" : "=l"(r) : "f"(a), "f"(b)); return r;
}
__device__ __forceinline__ ull fma2(ull a, ull b, ull c) {
    ull d; asm("fma.rn.f32x2 %0, %1, %2, %3;" : "=l"(d) : "l"(a), "l"(b), "l"(c));
    return d;
}
__device__ __forceinline__ void unpk2(ull v, float& lo, float& hi) {
    asm("mov.b64 {%0, %1}, %2;" : "=f"(lo), "=f"(hi) : "l"(v));
}
__device__ __forceinline__ void cp8(unsigned dst, const void* src) {
    ull g = (ull)__cvta_generic_to_global(src);
    asm volatile("cp.async.ca.shared.global [%0], [%1], 8;"
                 :: "r"(dst), "l"(g) : "memory");
}
__device__ __forceinline__ void sts_zero8(unsigned dst) {
    asm volatile("st.shared.v2.u32 [%0], {%1, %2};"
                 :: "r"(dst), "r"(0u), "r"(0u) : "memory");
}
#define CP_COMMIT() asm volatile("cp.async.commit_group;" ::: "memory")
#define CP_WAIT1()  asm volatile("cp.async.wait_group 1;" ::: "memory")

// ---- precompute ------------------------------------------------------------
__global__ void srf_precompute(const float* __restrict__ alphas,
                               const float* __restrict__ scales) {
    int tid = threadIdx.x;
    if (tid < NG) {
        const int FSarr[5] = {1, 1, 1, 2, 2};
        int s = tid;
        float mn = 0.2f * s, mx = mn + 0.2f;
        float sigma = (mx - mn) * 0.5f * tanhf(scales[s]) + (mn + mx) * 0.5f;
        int F = FSarr[s];
        int T = 2 * F + 1;
        float g[5];
        float sum = 0.f;
        for (int k = 0; k < T; ++k) {
            float x = (float)(k - F);
            g[k] = expf(-(x * x) / (2.f * sigma * sigma));
            sum += g[k];
        }
        float inv = 1.f / sum;
        float c1 = -1.f / (sigma * 1.41421356237309515f);
        for (int k = 0; k < 5; ++k) {
            float d0 = 0.f, d1 = 0.f, d2 = 0.f;
            if (k < T) {
                float x = (float)(k - F);
                float gg = g[k] * inv;
                float u = x / (sigma * 1.41421356237309515f);
                d0 = gg;
                d1 = c1 * (2.f * u) * gg;
                d2 = (c1 * c1) * (4.f * u * u - 2.f) * gg;
            }
            g_dp[s][0][k] = make_float2(d0, d0);
            g_dp[s][1][k] = make_float2(d1, d1);
            g_dp[s][2][k] = make_float2(d2, d2);
        }
    }
    for (int idx = tid; idx < NG * NB * ICG * OCG; idx += blockDim.x) {
        float a = alphas[idx];
        ((float2*)g_alpha)[idx] = make_float2(a, a);
    }
}

// ---- chunk prefetch: T rows into buf[c%3] ----------------------------------
template <int T>
__device__ __forceinline__ void prefetch_chunk(
    int c, int nc, int y0, unsigned sbase, const char* __restrict__ gbase,
    const int (&soff)[3], const int (&goff)[3], const int (&val)[3]) {
    constexpr int F = T / 2;
    if (c >= nc) return;   // caller still commits (empty group keeps counts)
    unsigned bufbase = sbase + (unsigned)((c % 3) * (T * ICG * SROW * 4));
#pragma unroll
    for (int u = 0; u < T; ++u) {
        int r = y0 - F + c * T + u;
        bool rv = (r >= 0 && r < H);
        unsigned sdst = bufbase + (unsigned)(u * (ICG * SROW * 4));
        const char* rowp = gbase + (size_t)(rv ? r : 0) * (W * 4);
#pragma unroll
        for (int j = 0; j < 3; ++j) {
            if (val[j] >= 0) {
                if (rv && val[j])
                    cp8(sdst + soff[j], rowp + goff[j]);
                else
                    sts_zero8(sdst + soff[j]);
            }
        }
    }
}

// ---- one row step (compute from staged smem, 4 out channels) ---------------
template <int T, bool HEAD>
__device__ __forceinline__ void row_step(
    int i, int u, int y0, int x0, int cp, int obase,
    const float* __restrict__ bb, float* __restrict__ outb,
    const ull (&dp)[3][T],
    const float2 (*__restrict__ sA)[ICG][OCG],
    ull (&acc)[T][OH]) {
    constexpr int F = T / 2;
    constexpr int OFF = 2 - F;
    const int IV[NB] = {0, 0, 0, 1, 1, 2};
    const int JH[NB] = {0, 1, 2, 0, 1, 0};
    const int NORD[NB] = {0, 3, 5, 1, 4, 2};   // iv pattern 0,1,2,0,1,0

    // mixing accumulators: [op-pair][lo/hi o][iv] — 12 independent chains
    ull m0[2][3], m1[2][3];
#pragma unroll
    for (int pp = 0; pp < 2; ++pp)
#pragma unroll
        for (int v = 0; v < 3; ++v) { m0[pp][v] = 0ULL; m1[pp][v] = 0ULL; }

    // per-channel: window -> 3 tap-sums (th) -> immediate mixing (hh killed)
#pragma unroll
    for (int ch = 0; ch < ICG; ++ch) {
        const float* p = bb + u * (ICG * SROW) + ch * SROW + 2 * cp;
        float2 A  = *(const float2*)(p);
        float2 Bv = *(const float2*)(p + 2);
        float2 C  = *(const float2*)(p + 4);
        float w[6] = {A.x, A.y, Bv.x, Bv.y, C.x, C.y};
        ull pkv[T];
#pragma unroll
        for (int k = 0; k < T; ++k) pkv[k] = pk2(w[OFF + k], w[OFF + k + 1]);
        ull th[3];
#pragma unroll
        for (int jh = 0; jh < 3; ++jh) {
            ull a = 0ULL;
#pragma unroll
            for (int k = 0; k < T; ++k) a = fma2(dp[jh][k], pkv[k], a);
            th[jh] = a;
        }
#pragma unroll
        for (int pp = 0; pp < 2; ++pp) {
            const int op = 2 * pp;
            ulonglong2 a[NB];
#pragma unroll
            for (int nn = 0; nn < NB; ++nn)
                a[nn] = *(const ulonglong2*)&sA[NORD[nn]][ch][obase + op];
#pragma unroll
            for (int nn = 0; nn < NB; ++nn) {
                const int n = NORD[nn];
                const int iv = IV[n], jh = JH[n];
                m0[pp][iv] = fma2(a[nn].x, th[jh], m0[pp][iv]);
                m1[pp][iv] = fma2(a[nn].y, th[jh], m1[pp][iv]);
            }
        }
    }

    // vertical scatter into accumulator ring
#pragma unroll
    for (int pp = 0; pp < 2; ++pp) {
        const int op = 2 * pp;
#pragma unroll
        for (int k = 0; k < T; ++k) {
            if (HEAD && k > i) continue;   // ghost-term guard (strip top)
            const int s = ((u - k + 2 * F) % T + T) % T;
            ull a0 = acc[s][op];
            a0 = fma2(dp[0][k], m0[pp][0], a0);
            a0 = fma2(dp[1][k], m0[pp][1], a0);
            a0 = fma2(dp[2][k], m0[pp][2], a0);
            acc[s][op] = a0;
            ull a1 = acc[s][op + 1];
            a1 = fma2(dp[0][k], m1[pp][0], a1);
            a1 = fma2(dp[1][k], m1[pp][1], a1);
            a1 = fma2(dp[2][k], m1[pp][2], a1);
            acc[s][op + 1] = a1;
        }
    }

    // store completed row (ring slot u == i mod T, chunks are T-aligned)
    if (i >= 2 * F && i < SH + 2 * F) {
        int y = y0 + i - 2 * F;
#pragma unroll
        for (int o = 0; o < OH; ++o) {
            float lo, hi;
            unpk2(acc[u][o], lo, hi);
            *(float2*)(outb + ((size_t)(obase + o) * H + y) * W + x0) =
                make_float2(lo, hi);
            acc[u][o] = 0ULL;
        }
    }
}

// ---- conv body -------------------------------------------------------------
template <int T>
__device__ __forceinline__ void srf_conv_body(
    const float* __restrict__ sIn, float* __restrict__ outb, int g,
    int x0, int cp, int obase, int y0, unsigned sbase,
    const char* __restrict__ gbase,
    const int (&soff)[3], const int (&goff)[3], const int (&val)[3],
    const float2 (*__restrict__ sA)[ICG][OCG]) {
    constexpr int F = T / 2;
    constexpr int ROWS = SH + 2 * F;
    constexpr int NC = (ROWS + T - 1) / T;      // chunks
    constexpr int LASTN = ROWS - (NC - 1) * T;  // rows in last chunk
    constexpr int BUFSTRIDE = T * ICG * SROW;   // floats per buffer

    ull dp[3][T];
#pragma unroll
    for (int d = 0; d < 3; ++d)
#pragma unroll
        for (int k = 0; k < T; ++k)
            dp[d][k] = *(const ull*)&g_dp[g][d][k];

    ull acc[T][OH];
#pragma unroll
    for (int s = 0; s < T; ++s)
#pragma unroll
        for (int o = 0; o < OH; ++o) acc[s][o] = 0ULL;

    // prologue: stage chunks 0 and 1
    prefetch_chunk<T>(0, NC, y0, sbase, gbase, soff, goff, val); CP_COMMIT();
    prefetch_chunk<T>(1, NC, y0, sbase, gbase, soff, goff, val); CP_COMMIT();

    // chunk 0 (head: ghost-term guard). One barrier per chunk: prefetch c+2
    // writes buffer (c+2)%3, whose last reader (chunk c-1) finished before
    // the top-of-c barrier in every thread's program order.
    CP_WAIT1();
    __syncthreads();
#pragma unroll
    for (int u = 0; u < T; ++u)
        row_step<T, true>(u, u, y0, x0, cp, obase, sIn, outb, dp, sA, acc);
    prefetch_chunk<T>(2, NC, y0, sbase, gbase, soff, goff, val); CP_COMMIT();

    // steady chunks
    for (int c = 1; c < NC - 1; ++c) {
        CP_WAIT1();
        __syncthreads();
        const float* bb = sIn + (c % 3) * BUFSTRIDE;
#pragma unroll
        for (int u = 0; u < T; ++u)
            row_step<T, false>(c * T + u, u, y0, x0, cp, obase, bb, outb,
                               dp, sA, acc);
        prefetch_chunk<T>(c + 2, NC, y0, sbase, gbase, soff, goff, val);
        CP_COMMIT();
    }

    // last (partial) chunk
    CP_WAIT1();
    __syncthreads();
    {
        const float* bb = sIn + ((NC - 1) % 3) * BUFSTRIDE;
#pragma unroll
        for (int u = 0; u < LASTN; ++u)
            row_step<T, false>((NC - 1) * T + u, u, y0, x0, cp, obase, bb,
                               outb, dp, sA, acc);
    }
}

// ---- combined conv kernel --------------------------------------------------
// grid: (3, H/SH, B*NG). 128 threads = 64 column pairs x 2 o-halves.
__global__ void __launch_bounds__(128, 3)
srf_conv_all(const float* __restrict__ in, float* __restrict__ out) {
    __shared__ __align__(16) float sIn[3 * 5 * ICG * SROW];  // 3 bufs, T=5
    __shared__ __align__(16) float2 sA[NB][ICG][OCG];

    int g = blockIdx.z % NG;
    int b = blockIdx.z / NG;
    int tid = threadIdx.x;
    int cp = tid & 63;                 // column pair
    int obase = (tid >> 6) * OH;       // 0 or 4
    int X0 = blockIdx.x * 128;
    int x0 = X0 + 2 * cp;
    int y0 = blockIdx.y * SH;

    const float* inb = in + ((size_t)b * INC + (size_t)g * ICG) * (H * W);
    float* outb      = out + ((size_t)b * OUTC + (size_t)g * OCG) * (H * W);

    {
        const float2* src = (const float2*)g_alpha[g];
        for (int idx = tid; idx < NB * ICG * OCG; idx += 128)
            ((float2*)sA)[idx] = src[idx];
    }

    // per-thread copy descriptors: float2 slots k = tid + 128*j over the
    // 4ch x 67-float2 row window [X0-2, X0+132)
    int soff[3], goff[3], val[3];
#pragma unroll
    for (int j = 0; j < 3; ++j) {
        int k = tid + 128 * j;
        if (k < NCP) {
            int ch = k / 67;
            int c2 = k % 67;
            int x = X0 - 2 + 2 * c2;
            bool xv = (x >= 0) && (x + 1 < W);
            soff[j] = (ch * SROW + 2 * c2) * 4;
            goff[j] = ch * (H * W * 4) + (xv ? x * 4 : 0);
            val[j] = xv ? 1 : 0;
        } else {
            soff[j] = 0; goff[j] = 0; val[j] = -1;
        }
    }
    unsigned sbase = (unsigned)__cvta_generic_to_shared(sIn);

    if (g < 3)
        srf_conv_body<3>(sIn, outb, g, x0, cp, obase, y0, sbase,
                         (const char*)inb, soff, goff, val, sA);
    else
        srf_conv_body<5>(sIn, outb, g, x0, cp, obase, y0, sbase,
                         (const char*)inb, soff, goff, val, sA);
}

extern "C" void kernel_launch(void* const* d_in, const int* in_sizes, int n_in,
                              void* d_out, int out_size) {
    const float* data   = (const float*)d_in[0];
    const float* alphas = (const float*)d_in[1];
    const float* scales = (const float*)d_in[2];
    float* out = (float*)d_out;

    srf_precompute<<<1, 256>>>(alphas, scales);

    dim3 blk(128, 1, 1);
    dim3 grid(3, H / SH, B * NG);
    srf_conv_all<<<grid, blk>>>(data, out);
}

// round 16
// speedup vs baseline: 1.1424x; 1.1424x over previous
#include <cuda_runtime.h>
#include <cuda_bf16.h>

// ---------------------------------------------------------------------------
// SRF layer: grouped conv, Gaussian-Hermite separable basis mixed by alphas.
// 128 threads/block = 64 column-pairs x 2 o-halves, paired as ADJACENT LANES
// (cp = tid>>1, oh = tid&1). R15 (re-bench after infra failure): horizontal
// pass split between the lane pair (each computes 2 of 4 channels, th
// exchanged via shfl.xor 1) — removes the duplicated horizontal work.
// Mixing/scatter/staging identical to R13: triple-buffered chunk staging,
// one __syncthreads per chunk; mixing per op-pair with alpha LDS.128
// batched; T-deep packed-f32x2 accumulator ring.
// ---------------------------------------------------------------------------

#define H 384
#define W 384
#define B 16
#define INC 20
#define OUTC 40
#define NG 5
#define ICG 4
#define OCG 8
#define OH 4           // out channels per thread (OCG/2)
#define NB 6
#define SH 32          // strip height (384/32 = 12 strips)
#define SROW 136       // smem floats per (row,ch) (134 used, padded)
#define NCP 268        // float2 copy slots per row (4ch x 67)

__device__ float2 g_dp[NG][3][5];
__device__ float2 g_alpha[NG][NB][ICG][OCG];

typedef unsigned long long ull;

__device__ __forceinline__ ull pk2(float a, float b) {
    ull r; asm("mov.b64 %0, {%1, %2};" : "=l"(r) : "f"(a), "f"(b)); return r;
}
__device__ __forceinline__ ull fma2(ull a, ull b, ull c) {
    ull d; asm("fma.rn.f32x2 %0, %1, %2, %3;" : "=l"(d) : "l"(a), "l"(b), "l"(c));
    return d;
}
__device__ __forceinline__ void unpk2(ull v, float& lo, float& hi) {
    asm("mov.b64 {%0, %1}, %2;" : "=f"(lo), "=f"(hi) : "l"(v));
}
__device__ __forceinline__ void cp8(unsigned dst, const void* src) {
    ull g = (ull)__cvta_generic_to_global(src);
    asm volatile("cp.async.ca.shared.global [%0], [%1], 8;"
                 :: "r"(dst), "l"(g) : "memory");
}
__device__ __forceinline__ void sts_zero8(unsigned dst) {
    asm volatile("st.shared.v2.u32 [%0], {%1, %2};"
                 :: "r"(dst), "r"(0u), "r"(0u) : "memory");
}
#define CP_COMMIT() asm volatile("cp.async.commit_group;" ::: "memory")
#define CP_WAIT1()  asm volatile("cp.async.wait_group 1;" ::: "memory")

// ---- precompute ------------------------------------------------------------
__global__ void srf_precompute(const float* __restrict__ alphas,
                               const float* __restrict__ scales) {
    int tid = threadIdx.x;
    if (tid < NG) {
        const int FSarr[5] = {1, 1, 1, 2, 2};
        int s = tid;
        float mn = 0.2f * s, mx = mn + 0.2f;
        float sigma = (mx - mn) * 0.5f * tanhf(scales[s]) + (mn + mx) * 0.5f;
        int F = FSarr[s];
        int T = 2 * F + 1;
        float g[5];
        float sum = 0.f;
        for (int k = 0; k < T; ++k) {
            float x = (float)(k - F);
            g[k] = expf(-(x * x) / (2.f * sigma * sigma));
            sum += g[k];
        }
        float inv = 1.f / sum;
        float c1 = -1.f / (sigma * 1.41421356237309515f);
        for (int k = 0; k < 5; ++k) {
            float d0 = 0.f, d1 = 0.f, d2 = 0.f;
            if (k < T) {
                float x = (float)(k - F);
                float gg = g[k] * inv;
                float u = x / (sigma * 1.41421356237309515f);
                d0 = gg;
                d1 = c1 * (2.f * u) * gg;
                d2 = (c1 * c1) * (4.f * u * u - 2.f) * gg;
            }
            g_dp[s][0][k] = make_float2(d0, d0);
            g_dp[s][1][k] = make_float2(d1, d1);
            g_dp[s][2][k] = make_float2(d2, d2);
        }
    }
    for (int idx = tid; idx < NG * NB * ICG * OCG; idx += blockDim.x) {
        float a = alphas[idx];
        ((float2*)g_alpha)[idx] = make_float2(a, a);
    }
}

// ---- chunk prefetch: T rows into buf[c%3] ----------------------------------
template <int T>
__device__ __forceinline__ void prefetch_chunk(
    int c, int nc, int y0, unsigned sbase, const char* __restrict__ gbase,
    const int (&soff)[3], const int (&goff)[3], const int (&val)[3]) {
    constexpr int F = T / 2;
    if (c >= nc) return;   // caller still commits (empty group keeps counts)
    unsigned bufbase = sbase + (unsigned)((c % 3) * (T * ICG * SROW * 4));
#pragma unroll
    for (int u = 0; u < T; ++u) {
        int r = y0 - F + c * T + u;
        bool rv = (r >= 0 && r < H);
        unsigned sdst = bufbase + (unsigned)(u * (ICG * SROW * 4));
        const char* rowp = gbase + (size_t)(rv ? r : 0) * (W * 4);
#pragma unroll
        for (int j = 0; j < 3; ++j) {
            if (val[j] >= 0) {
                if (rv && val[j])
                    cp8(sdst + soff[j], rowp + goff[j]);
                else
                    sts_zero8(sdst + soff[j]);
            }
        }
    }
}

// ---- one row step (compute from staged smem, 4 out channels) ---------------
template <int T, bool HEAD>
__device__ __forceinline__ void row_step(
    int i, int u, int y0, int x0, int cp, int chOwn, int chOth, int obase,
    const float* __restrict__ bb, float* __restrict__ outb,
    const ull (&dp)[3][T],
    const float2 (*__restrict__ sA)[ICG][OCG],
    ull (&acc)[T][OH]) {
    constexpr int F = T / 2;
    constexpr int OFF = 2 - F;
    const int IV[NB] = {0, 0, 0, 1, 1, 2};
    const int JH[NB] = {0, 1, 2, 0, 1, 0};
    const int NORD[NB] = {0, 3, 5, 1, 4, 2};   // iv pattern 0,1,2,0,1,0

    // horizontal pass: this lane computes channels chOwn, chOwn+1 only
    ull thp[2][3];
#pragma unroll
    for (int cc = 0; cc < 2; ++cc) {
        const float* p = bb + u * (ICG * SROW) + (chOwn + cc) * SROW + 2 * cp;
        float2 A  = *(const float2*)(p);
        float2 Bv = *(const float2*)(p + 2);
        float2 C  = *(const float2*)(p + 4);
        float w[6] = {A.x, A.y, Bv.x, Bv.y, C.x, C.y};
        ull pkv[T];
#pragma unroll
        for (int k = 0; k < T; ++k) pkv[k] = pk2(w[OFF + k], w[OFF + k + 1]);
#pragma unroll
        for (int jh = 0; jh < 3; ++jh) {
            ull a = 0ULL;
#pragma unroll
            for (int k = 0; k < T; ++k) a = fma2(dp[jh][k], pkv[k], a);
            thp[cc][jh] = a;
        }
    }

    // exchange with partner lane (xor 1): partner owns channels chOth,chOth+1
    ull tho[2][3];
#pragma unroll
    for (int cc = 0; cc < 2; ++cc)
#pragma unroll
        for (int jh = 0; jh < 3; ++jh)
            tho[cc][jh] = __shfl_xor_sync(0xffffffffu, thp[cc][jh], 1);

    // per-o-pair mixing fused with vertical scatter (this thread's 4 o's)
    // R13 structure: alpha loads batched; register indices compile-time,
    // runtime channel ids appear only in LDS addresses.
#pragma unroll
    for (int op = 0; op < OH; op += 2) {
        ull m0[3] = {0ULL, 0ULL, 0ULL};
        ull m1[3] = {0ULL, 0ULL, 0ULL};
#pragma unroll
        for (int nn = 0; nn < NB; ++nn) {
            const int n  = NORD[nn];
            const int iv = IV[n], jh = JH[n];
            ulonglong2 a0 = *(const ulonglong2*)&sA[n][chOwn    ][obase + op];
            ulonglong2 a1 = *(const ulonglong2*)&sA[n][chOwn + 1][obase + op];
            ulonglong2 a2 = *(const ulonglong2*)&sA[n][chOth    ][obase + op];
            ulonglong2 a3 = *(const ulonglong2*)&sA[n][chOth + 1][obase + op];
            m0[iv] = fma2(a0.x, thp[0][jh], m0[iv]);
            m1[iv] = fma2(a0.y, thp[0][jh], m1[iv]);
            m0[iv] = fma2(a1.x, thp[1][jh], m0[iv]);
            m1[iv] = fma2(a1.y, thp[1][jh], m1[iv]);
            m0[iv] = fma2(a2.x, tho[0][jh], m0[iv]);
            m1[iv] = fma2(a2.y, tho[0][jh], m1[iv]);
            m0[iv] = fma2(a3.x, tho[1][jh], m0[iv]);
            m1[iv] = fma2(a3.y, tho[1][jh], m1[iv]);
        }
#pragma unroll
        for (int k = 0; k < T; ++k) {
            if (HEAD && k > i) continue;   // ghost-term guard (strip top)
            const int s = ((u - k + 2 * F) % T + T) % T;
            ull a0 = acc[s][op];
            a0 = fma2(dp[0][k], m0[0], a0);
            a0 = fma2(dp[1][k], m0[1], a0);
            a0 = fma2(dp[2][k], m0[2], a0);
            acc[s][op] = a0;
            ull a1 = acc[s][op + 1];
            a1 = fma2(dp[0][k], m1[0], a1);
            a1 = fma2(dp[1][k], m1[1], a1);
            a1 = fma2(dp[2][k], m1[2], a1);
            acc[s][op + 1] = a1;
        }
    }

    // store completed row (ring slot u == i mod T, chunks are T-aligned)
    if (i >= 2 * F && i < SH + 2 * F) {
        int y = y0 + i - 2 * F;
#pragma unroll
        for (int o = 0; o < OH; ++o) {
            float lo, hi;
            unpk2(acc[u][o], lo, hi);
            *(float2*)(outb + ((size_t)(obase + o) * H + y) * W + x0) =
                make_float2(lo, hi);
            acc[u][o] = 0ULL;
        }
    }
}

// ---- conv body -------------------------------------------------------------
template <int T>
__device__ __forceinline__ void srf_conv_body(
    const float* __restrict__ sIn, float* __restrict__ outb, int g,
    int x0, int cp, int chOwn, int chOth, int obase, int y0, unsigned sbase,
    const char* __restrict__ gbase,
    const int (&soff)[3], const int (&goff)[3], const int (&val)[3],
    const float2 (*__restrict__ sA)[ICG][OCG]) {
    constexpr int F = T / 2;
    constexpr int ROWS = SH + 2 * F;
    constexpr int NC = (ROWS + T - 1) / T;      // chunks
    constexpr int LASTN = ROWS - (NC - 1) * T;  // rows in last chunk
    constexpr int BUFSTRIDE = T * ICG * SROW;   // floats per buffer

    ull dp[3][T];
#pragma unroll
    for (int d = 0; d < 3; ++d)
#pragma unroll
        for (int k = 0; k < T; ++k)
            dp[d][k] = *(const ull*)&g_dp[g][d][k];

    ull acc[T][OH];
#pragma unroll
    for (int s = 0; s < T; ++s)
#pragma unroll
        for (int o = 0; o < OH; ++o) acc[s][o] = 0ULL;

    // prologue: stage chunks 0 and 1
    prefetch_chunk<T>(0, NC, y0, sbase, gbase, soff, goff, val); CP_COMMIT();
    prefetch_chunk<T>(1, NC, y0, sbase, gbase, soff, goff, val); CP_COMMIT();

    // chunk 0 (head: ghost-term guard). One barrier per chunk: prefetch c+2
    // writes buffer (c+2)%3, whose last reader (chunk c-1) finished before
    // the top-of-c barrier in every thread's program order.
    CP_WAIT1();
    __syncthreads();
#pragma unroll
    for (int u = 0; u < T; ++u)
        row_step<T, true>(u, u, y0, x0, cp, chOwn, chOth, obase, sIn, outb,
                          dp, sA, acc);
    prefetch_chunk<T>(2, NC, y0, sbase, gbase, soff, goff, val); CP_COMMIT();

    // steady chunks
    for (int c = 1; c < NC - 1; ++c) {
        CP_WAIT1();
        __syncthreads();
        const float* bb = sIn + (c % 3) * BUFSTRIDE;
#pragma unroll
        for (int u = 0; u < T; ++u)
            row_step<T, false>(c * T + u, u, y0, x0, cp, chOwn, chOth, obase,
                               bb, outb, dp, sA, acc);
        prefetch_chunk<T>(c + 2, NC, y0, sbase, gbase, soff, goff, val);
        CP_COMMIT();
    }

    // last (partial) chunk
    CP_WAIT1();
    __syncthreads();
    {
        const float* bb = sIn + ((NC - 1) % 3) * BUFSTRIDE;
#pragma unroll
        for (int u = 0; u < LASTN; ++u)
            row_step<T, false>((NC - 1) * T + u, u, y0, x0, cp, chOwn, chOth,
                               obase, bb, outb, dp, sA, acc);
    }
}

// ---- combined conv kernel --------------------------------------------------
// grid: (3, H/SH, B*NG). 128 threads = 64 column pairs x 2 o-halves, o-half
// partners are ADJACENT LANES so the horizontal pass can be split + shfl'd.
__global__ void __launch_bounds__(128, 3)
srf_conv_all(const float* __restrict__ in, float* __restrict__ out) {
    __shared__ __align__(16) float sIn[3 * 5 * ICG * SROW];  // 3 bufs, T=5
    __shared__ __align__(16) float2 sA[NB][ICG][OCG];

    int g = blockIdx.z % NG;
    int b = blockIdx.z / NG;
    int tid = threadIdx.x;
    int cp = tid >> 1;                 // column pair (0..63)
    int oh = tid & 1;                  // o-half (lane parity)
    int obase = oh * OH;               // 0 or 4
    int chOwn = 2 * oh;                // this lane's horizontal channels
    int chOth = 2 * (oh ^ 1);          // partner's channels
    int X0 = blockIdx.x * 128;
    int x0 = X0 + 2 * cp;
    int y0 = blockIdx.y * SH;

    const float* inb = in + ((size_t)b * INC + (size_t)g * ICG) * (H * W);
    float* outb      = out + ((size_t)b * OUTC + (size_t)g * OCG) * (H * W);

    {
        const float2* src = (const float2*)g_alpha[g];
        for (int idx = tid; idx < NB * ICG * OCG; idx += 128)
            ((float2*)sA)[idx] = src[idx];
    }

    // per-thread copy descriptors: float2 slots k = tid + 128*j over the
    // 4ch x 67-float2 row window [X0-2, X0+132)
    int soff[3], goff[3], val[3];
#pragma unroll
    for (int j = 0; j < 3; ++j) {
        int k = tid + 128 * j;
        if (k < NCP) {
            int ch = k / 67;
            int c2 = k % 67;
            int x = X0 - 2 + 2 * c2;
            bool xv = (x >= 0) && (x + 1 < W);
            soff[j] = (ch * SROW + 2 * c2) * 4;
            goff[j] = ch * (H * W * 4) + (xv ? x * 4 : 0);
            val[j] = xv ? 1 : 0;
        } else {
            soff[j] = 0; goff[j] = 0; val[j] = -1;
        }
    }
    unsigned sbase = (unsigned)__cvta_generic_to_shared(sIn);

    if (g < 3)
        srf_conv_body<3>(sIn, outb, g, x0, cp, chOwn, chOth, obase, y0, sbase,
                         (const char*)inb, soff, goff, val, sA);
    else
        srf_conv_body<5>(sIn, outb, g, x0, cp, chOwn, chOth, obase, y0, sbase,
                         (const char*)inb, soff, goff, val, sA);
}

extern "C" void kernel_launch(void* const* d_in, const int* in_sizes, int n_in,
                              void* d_out, int out_size) {
    const float* data   = (const float*)d_in[0];
    const float* alphas = (const float*)d_in[1];
    const float* scales = (const float*)d_in[2];
    float* out = (float*)d_out;

    srf_precompute<<<1, 256>>>(alphas, scales);

    dim3 blk(128, 1, 1);
    dim3 grid(3, H / SH, B * NG);
    srf_conv_all<<<grid, blk>>>(data, out);
}

// round 17
// speedup vs baseline: 2.3560x; 2.0623x over previous
#include <cuda_runtime.h>
#include <cuda_bf16.h>

// ---------------------------------------------------------------------------
// SRF layer: grouped conv, Gaussian-Hermite separable basis mixed by alphas.
// R17: 4-way lane split. 128 threads = 32 column-pairs x 4 o-quarters
// (cp = tid>>2, oq = tid&3). Each thread owns 2 output channels (acc[T][2])
// and computes horizontal taps for 1 input channel; the other 3 channels'
// taps arrive via shfl_xor rounds r=1..3 (partner oq^r owns channel oq^r).
// Register state halves -> 4 blocks/SM (16 warps). Staging identical to the
// verified R12/R16 pipeline: triple-buffered chunk staging (chunk = T rows,
// cp.async, wait_group 1, ONE __syncthreads per chunk).
// ---------------------------------------------------------------------------

#define H 384
#define W 384
#define B 16
#define INC 20
#define OUTC 40
#define NG 5
#define ICG 4
#define OCG 8
#define OQ 2           // out channels per thread (OCG/4)
#define NB 6
#define SH 32          // strip height (384/32 = 12 strips)
#define SROW 72        // smem floats per (row,ch): window [X0-2, X0+68)
#define NCP 140        // float2 copy slots per row (4ch x 35)

__device__ float2 g_dp[NG][3][5];
__device__ float2 g_alpha[NG][NB][ICG][OCG];

typedef unsigned long long ull;

__device__ __forceinline__ ull pk2(float a, float b) {
    ull r; asm("mov.b64 %0, {%1, %2};" : "=l"(r) : "f"(a), "f"(b)); return r;
}
__device__ __forceinline__ ull fma2(ull a, ull b, ull c) {
    ull d; asm("fma.rn.f32x2 %0, %1, %2, %3;" : "=l"(d) : "l"(a), "l"(b), "l"(c));
    return d;
}
__device__ __forceinline__ void unpk2(ull v, float& lo, float& hi) {
    asm("mov.b64 {%0, %1}, %2;" : "=f"(lo), "=f"(hi) : "l"(v));
}
__device__ __forceinline__ void cp8(unsigned dst, const void* src) {
    ull g = (ull)__cvta_generic_to_global(src);
    asm volatile("cp.async.ca.shared.global [%0], [%1], 8;"
                 :: "r"(dst), "l"(g) : "memory");
}
__device__ __forceinline__ void sts_zero8(unsigned dst) {
    asm volatile("st.shared.v2.u32 [%0], {%1, %2};"
                 :: "r"(dst), "r"(0u), "r"(0u) : "memory");
}
#define CP_COMMIT() asm volatile("cp.async.commit_group;" ::: "memory")
#define CP_WAIT1()  asm volatile("cp.async.wait_group 1;" ::: "memory")

// ---- precompute ------------------------------------------------------------
__global__ void srf_precompute(const float* __restrict__ alphas,
                               const float* __restrict__ scales) {
    int tid = threadIdx.x;
    if (tid < NG) {
        const int FSarr[5] = {1, 1, 1, 2, 2};
        int s = tid;
        float mn = 0.2f * s, mx = mn + 0.2f;
        float sigma = (mx - mn) * 0.5f * tanhf(scales[s]) + (mn + mx) * 0.5f;
        int F = FSarr[s];
        int T = 2 * F + 1;
        float g[5];
        float sum = 0.f;
        for (int k = 0; k < T; ++k) {
            float x = (float)(k - F);
            g[k] = expf(-(x * x) / (2.f * sigma * sigma));
            sum += g[k];
        }
        float inv = 1.f / sum;
        float c1 = -1.f / (sigma * 1.41421356237309515f);
        for (int k = 0; k < 5; ++k) {
            float d0 = 0.f, d1 = 0.f, d2 = 0.f;
            if (k < T) {
                float x = (float)(k - F);
                float gg = g[k] * inv;
                float u = x / (sigma * 1.41421356237309515f);
                d0 = gg;
                d1 = c1 * (2.f * u) * gg;
                d2 = (c1 * c1) * (4.f * u * u - 2.f) * gg;
            }
            g_dp[s][0][k] = make_float2(d0, d0);
            g_dp[s][1][k] = make_float2(d1, d1);
            g_dp[s][2][k] = make_float2(d2, d2);
        }
    }
    for (int idx = tid; idx < NG * NB * ICG * OCG; idx += blockDim.x) {
        float a = alphas[idx];
        ((float2*)g_alpha)[idx] = make_float2(a, a);
    }
}

// ---- chunk prefetch: T rows into buf[c%3] ----------------------------------
template <int T>
__device__ __forceinline__ void prefetch_chunk(
    int c, int nc, int y0, unsigned sbase, const char* __restrict__ gbase,
    const int (&soff)[2], const int (&goff)[2], const int (&val)[2]) {
    constexpr int F = T / 2;
    if (c >= nc) return;   // caller still commits (empty group keeps counts)
    unsigned bufbase = sbase + (unsigned)((c % 3) * (T * ICG * SROW * 4));
#pragma unroll
    for (int u = 0; u < T; ++u) {
        int r = y0 - F + c * T + u;
        bool rv = (r >= 0 && r < H);
        unsigned sdst = bufbase + (unsigned)(u * (ICG * SROW * 4));
        const char* rowp = gbase + (size_t)(rv ? r : 0) * (W * 4);
#pragma unroll
        for (int j = 0; j < 2; ++j) {
            if (val[j] >= 0) {
                if (rv && val[j])
                    cp8(sdst + soff[j], rowp + goff[j]);
                else
                    sts_zero8(sdst + soff[j]);
            }
        }
    }
}

// ---- one row step (compute from staged smem, 2 out channels) ---------------
template <int T, bool HEAD>
__device__ __forceinline__ void row_step(
    int i, int u, int y0, int x0, int cp, int oq, int obase,
    const float* __restrict__ bb, float* __restrict__ outb,
    const ull (&dp)[3][T],
    const float2 (*__restrict__ sA)[ICG][OCG],
    ull (&acc)[T][OQ]) {
    constexpr int F = T / 2;
    constexpr int OFF = 2 - F;
    const int IV[NB] = {0, 0, 0, 1, 1, 2};
    const int JH[NB] = {0, 1, 2, 0, 1, 0};
    const int NORD[NB] = {0, 3, 5, 1, 4, 2};   // iv pattern 0,1,2,0,1,0

    // horizontal pass: this lane computes channel oq only
    ull thp[3];
    {
        const float* p = bb + u * (ICG * SROW) + oq * SROW + 2 * cp;
        float2 A  = *(const float2*)(p);
        float2 Bv = *(const float2*)(p + 2);
        float2 C  = *(const float2*)(p + 4);
        float w[6] = {A.x, A.y, Bv.x, Bv.y, C.x, C.y};
        ull pkv[T];
#pragma unroll
        for (int k = 0; k < T; ++k) pkv[k] = pk2(w[OFF + k], w[OFF + k + 1]);
#pragma unroll
        for (int jh = 0; jh < 3; ++jh) {
            ull a = 0ULL;
#pragma unroll
            for (int k = 0; k < T; ++k) a = fma2(dp[jh][k], pkv[k], a);
            thp[jh] = a;
        }
    }

    // mixing: 4 rounds. Round r uses channel oq^r, whose taps live in lane
    // xor r (that lane's oq is our oq^r). m0/m1 = this lane's 2 o-channels.
    ull m0[3] = {0ULL, 0ULL, 0ULL};
    ull m1[3] = {0ULL, 0ULL, 0ULL};
#pragma unroll
    for (int r = 0; r < 4; ++r) {
        const int ch = oq ^ r;
        ull th[3];
#pragma unroll
        for (int jh = 0; jh < 3; ++jh)
            th[jh] = (r == 0) ? thp[jh]
                              : __shfl_xor_sync(0xffffffffu, thp[jh], r);
        ulonglong2 a[NB];
#pragma unroll
        for (int nn = 0; nn < NB; ++nn)
            a[nn] = *(const ulonglong2*)&sA[NORD[nn]][ch][obase];
#pragma unroll
        for (int nn = 0; nn < NB; ++nn) {
            const int n = NORD[nn];
            const int iv = IV[n], jh = JH[n];
            m0[iv] = fma2(a[nn].x, th[jh], m0[iv]);
            m1[iv] = fma2(a[nn].y, th[jh], m1[iv]);
        }
    }

    // vertical scatter into accumulator ring
#pragma unroll
    for (int k = 0; k < T; ++k) {
        if (HEAD && k > i) continue;   // ghost-term guard (strip top)
        const int s = ((u - k + 2 * F) % T + T) % T;
        ull a0 = acc[s][0];
        a0 = fma2(dp[0][k], m0[0], a0);
        a0 = fma2(dp[1][k], m0[1], a0);
        a0 = fma2(dp[2][k], m0[2], a0);
        acc[s][0] = a0;
        ull a1 = acc[s][1];
        a1 = fma2(dp[0][k], m1[0], a1);
        a1 = fma2(dp[1][k], m1[1], a1);
        a1 = fma2(dp[2][k], m1[2], a1);
        acc[s][1] = a1;
    }

    // store completed row (ring slot u == i mod T, chunks are T-aligned)
    if (i >= 2 * F && i < SH + 2 * F) {
        int y = y0 + i - 2 * F;
#pragma unroll
        for (int o = 0; o < OQ; ++o) {
            float lo, hi;
            unpk2(acc[u][o], lo, hi);
            *(float2*)(outb + ((size_t)(obase + o) * H + y) * W + x0) =
                make_float2(lo, hi);
            acc[u][o] = 0ULL;
        }
    }
}

// ---- conv body -------------------------------------------------------------
template <int T>
__device__ __forceinline__ void srf_conv_body(
    const float* __restrict__ sIn, float* __restrict__ outb, int g,
    int x0, int cp, int oq, int obase, int y0, unsigned sbase,
    const char* __restrict__ gbase,
    const int (&soff)[2], const int (&goff)[2], const int (&val)[2],
    const float2 (*__restrict__ sA)[ICG][OCG]) {
    constexpr int F = T / 2;
    constexpr int ROWS = SH + 2 * F;
    constexpr int NC = (ROWS + T - 1) / T;      // chunks
    constexpr int LASTN = ROWS - (NC - 1) * T;  // rows in last chunk
    constexpr int BUFSTRIDE = T * ICG * SROW;   // floats per buffer

    ull dp[3][T];
#pragma unroll
    for (int d = 0; d < 3; ++d)
#pragma unroll
        for (int k = 0; k < T; ++k)
            dp[d][k] = *(const ull*)&g_dp[g][d][k];

    ull acc[T][OQ];
#pragma unroll
    for (int s = 0; s < T; ++s)
#pragma unroll
        for (int o = 0; o < OQ; ++o) acc[s][o] = 0ULL;

    // prologue: stage chunks 0 and 1
    prefetch_chunk<T>(0, NC, y0, sbase, gbase, soff, goff, val); CP_COMMIT();
    prefetch_chunk<T>(1, NC, y0, sbase, gbase, soff, goff, val); CP_COMMIT();

    // chunk 0 (head: ghost-term guard). One barrier per chunk: prefetch c+2
    // writes buffer (c+2)%3, whose last reader (chunk c-1) finished before
    // the top-of-c barrier in every thread's program order.
    CP_WAIT1();
    __syncthreads();
#pragma unroll
    for (int u = 0; u < T; ++u)
        row_step<T, true>(u, u, y0, x0, cp, oq, obase, sIn, outb, dp, sA, acc);
    prefetch_chunk<T>(2, NC, y0, sbase, gbase, soff, goff, val); CP_COMMIT();

    // steady chunks
    for (int c = 1; c < NC - 1; ++c) {
        CP_WAIT1();
        __syncthreads();
        const float* bb = sIn + (c % 3) * BUFSTRIDE;
#pragma unroll
        for (int u = 0; u < T; ++u)
            row_step<T, false>(c * T + u, u, y0, x0, cp, oq, obase, bb, outb,
                               dp, sA, acc);
        prefetch_chunk<T>(c + 2, NC, y0, sbase, gbase, soff, goff, val);
        CP_COMMIT();
    }

    // last (partial) chunk
    CP_WAIT1();
    __syncthreads();
    {
        const float* bb = sIn + ((NC - 1) % 3) * BUFSTRIDE;
#pragma unroll
        for (int u = 0; u < LASTN; ++u)
            row_step<T, false>((NC - 1) * T + u, u, y0, x0, cp, oq, obase, bb,
                               outb, dp, sA, acc);
    }
}

// ---- combined conv kernel --------------------------------------------------
// grid: (6, H/SH, B*NG). 128 threads = 32 column pairs x 4 o-quarters.
__global__ void __launch_bounds__(128, 4)
srf_conv_all(const float* __restrict__ in, float* __restrict__ out) {
    __shared__ __align__(16) float sIn[3 * 5 * ICG * SROW];  // 3 bufs, T=5
    __shared__ __align__(16) float2 sA[NB][ICG][OCG];

    int g = blockIdx.z % NG;
    int b = blockIdx.z / NG;
    int tid = threadIdx.x;
    int cp = tid >> 2;                 // column pair (0..31)
    int oq = tid & 3;                  // o-quarter / owned input channel
    int obase = oq * OQ;               // 0,2,4,6
    int X0 = blockIdx.x * 64;
    int x0 = X0 + 2 * cp;
    int y0 = blockIdx.y * SH;

    const float* inb = in + ((size_t)b * INC + (size_t)g * ICG) * (H * W);
    float* outb      = out + ((size_t)b * OUTC + (size_t)g * OCG) * (H * W);

    {
        const float2* src = (const float2*)g_alpha[g];
        for (int idx = tid; idx < NB * ICG * OCG; idx += 128)
            ((float2*)sA)[idx] = src[idx];
    }

    // per-thread copy descriptors: float2 slots k = tid + 128*j over the
    // 4ch x 35-float2 row window [X0-2, X0+68)
    int soff[2], goff[2], val[2];
#pragma unroll
    for (int j = 0; j < 2; ++j) {
        int k = tid + 128 * j;
        if (k < NCP) {
            int ch = k / 35;
            int c2 = k % 35;
            int x = X0 - 2 + 2 * c2;
            bool xv = (x >= 0) && (x + 1 < W);
            soff[j] = (ch * SROW + 2 * c2) * 4;
            goff[j] = ch * (H * W * 4) + (xv ? x * 4 : 0);
            val[j] = xv ? 1 : 0;
        } else {
            soff[j] = 0; goff[j] = 0; val[j] = -1;
        }
    }
    unsigned sbase = (unsigned)__cvta_generic_to_shared(sIn);

    if (g < 3)
        srf_conv_body<3>(sIn, outb, g, x0, cp, oq, obase, y0, sbase,
                         (const char*)inb, soff, goff, val, sA);
    else
        srf_conv_body<5>(sIn, outb, g, x0, cp, oq, obase, y0, sbase,
                         (const char*)inb, soff, goff, val, sA);
}

extern "C" void kernel_launch(void* const* d_in, const int* in_sizes, int n_in,
                              void* d_out, int out_size) {
    const float* data   = (const float*)d_in[0];
    const float* alphas = (const float*)d_in[1];
    const float* scales = (const float*)d_in[2];
    float* out = (float*)d_out;

    srf_precompute<<<1, 256>>>(alphas, scales);

    dim3 blk(128, 1, 1);
    dim3 grid(6, H / SH, B * NG);
    srf_conv_all<<<grid, blk>>>(data, out);
}